// round 1
// baseline (speedup 1.0000x reference)
#include <cuda_runtime.h>
#include <math.h>

// ---------------- problem constants ----------------
#define BB   8
#define TT   16
#define CINC 16
#define HID  64
#define CH   (CINC + HID)   // 80
#define HH   64
#define WW   64
#define NPIX (HH * WW)
#define NOUT (BB * HID * NPIX)   // 2,097,152 per tensor

// tiling
#define OCG   8     // output channels per block
#define CCH   16    // input-channel chunk (80 = 5 * 16)
#define PATCH 18    // 16 + 2 halo

// double-buffered recurrent state (allocation-free scratch)
__device__ float g_h[2][NOUT];
__device__ float g_c[2][NOUT];

__device__ __forceinline__ float sigf(float x) {
    return 1.0f / (1.0f + __expf(-x));
}
__device__ __forceinline__ float tanhg(float x) {
    // 2*sigmoid(2x)-1 ; saturates correctly for |x| large (exp->inf/0)
    return 2.0f / (1.0f + __expf(-2.0f * x)) - 1.0f;
}

__global__ void zero_state_kernel() {
    int i = blockIdx.x * blockDim.x + threadIdx.x;
    if (i < NOUT) {
        g_h[0][i] = 0.0f;
        g_c[0][i] = 0.0f;
    }
}

// One ConvLSTM step, fused: 3x conv3x3 gates + channel-linear o-gate + state update.
// Grid: (4, 4, BB * HID/OCG). Block: 256 threads = 16x16 spatial tile.
__global__ __launch_bounds__(256, 2)
void step_kernel(const float* __restrict__ x, int t,
                 const float* __restrict__ Wf, const float* __restrict__ bf,
                 const float* __restrict__ Wi, const float* __restrict__ bi,
                 const float* __restrict__ Wc, const float* __restrict__ bc,
                 const float* __restrict__ Wo, const float* __restrict__ bo,
                 int src,
                 float* __restrict__ h_out, float* __restrict__ c_out)
{
    __shared__ float  s_in[CCH][PATCH * PATCH];       // 20.25 KB
    __shared__ float4 s_w[CCH * OCG * 7];             // 14 KB: per (c,oc): 27 conv w + 1 lin w

    const int tid = threadIdx.x;
    const int tx = tid & 15, ty = tid >> 4;
    const int bx = blockIdx.x, by = blockIdx.y;
    const int b   = blockIdx.z >> 3;
    const int oc0 = (blockIdx.z & 7) * OCG;
    const int gx = bx * 16 + tx, gy = by * 16 + ty;

    const float* __restrict__ h_prev = g_h[src];
    const float* __restrict__ c_prev = g_c[src];

    float accf[OCG], acci[OCG], accg[OCG], acco[OCG];
#pragma unroll
    for (int k = 0; k < OCG; ++k) { accf[k] = 0.f; acci[k] = 0.f; accg[k] = 0.f; acco[k] = 0.f; }

    for (int cb = 0; cb < CH; cb += CCH) {
        // --- cooperative load: input patch (16 ch x 18x18, zero-padded SAME) ---
        for (int i = tid; i < CCH * PATCH * PATCH; i += 256) {
            int c = i / (PATCH * PATCH);
            int r = i - c * (PATCH * PATCH);
            int py = r / PATCH, px = r - py * PATCH;
            int iy = by * 16 + py - 1, ix = bx * 16 + px - 1;
            float v = 0.0f;
            if ((unsigned)iy < HH && (unsigned)ix < WW) {
                int cc = cb + c;
                v = (cc < CINC)
                    ? x[(((size_t)(b * TT + t) * CINC + cc) * HH + iy) * WW + ix]
                    : h_prev[(((size_t)b * HID + (cc - CINC)) * HH + iy) * WW + ix];
            }
            s_in[c][r] = v;
        }
        // --- cooperative load: packed weights [c][oc][28] (float4-aligned) ---
        {
            float* sw = (float*)s_w;
            for (int i = tid; i < CCH * OCG * 28; i += 256) {
                int co = i / 28;
                int j  = i - co * 28;
                int c  = co >> 3, oc = co & 7;
                int cc = cb + c, occ = oc0 + oc;
                float w;
                if (j < 9)       w = Wf[(occ * CH + cc) * 9 + j];
                else if (j < 18) w = Wi[(occ * CH + cc) * 9 + (j - 9)];
                else if (j < 27) w = Wc[(occ * CH + cc) * 9 + (j - 18)];
                else             w = Wo[occ * CH + cc];
                sw[i] = w;
            }
        }
        __syncthreads();

#pragma unroll
        for (int c = 0; c < CCH; ++c) {
            const float* p = &s_in[c][ty * PATCH + tx];
            float v0 = p[0],           v1 = p[1],             v2 = p[2];
            float v3 = p[PATCH],       v4 = p[PATCH + 1],     v5 = p[PATCH + 2];
            float v6 = p[2 * PATCH],   v7 = p[2 * PATCH + 1], v8 = p[2 * PATCH + 2];
            const float4* wp = &s_w[c * OCG * 7];
#pragma unroll
            for (int oc = 0; oc < OCG; ++oc) {
                float4 w0 = wp[oc * 7 + 0];
                float4 w1 = wp[oc * 7 + 1];
                float4 w2 = wp[oc * 7 + 2];
                float4 w3 = wp[oc * 7 + 3];
                float4 w4 = wp[oc * 7 + 4];
                float4 w5 = wp[oc * 7 + 5];
                float4 w6 = wp[oc * 7 + 6];
                accf[oc] += w0.x*v0 + w0.y*v1 + w0.z*v2 + w0.w*v3 + w1.x*v4
                          + w1.y*v5 + w1.z*v6 + w1.w*v7 + w2.x*v8;
                acci[oc] += w2.y*v0 + w2.z*v1 + w2.w*v2 + w3.x*v3 + w3.y*v4
                          + w3.z*v5 + w3.w*v6 + w4.x*v7 + w4.y*v8;
                accg[oc] += w4.z*v0 + w4.w*v1 + w5.x*v2 + w5.y*v3 + w5.z*v4
                          + w5.w*v5 + w6.x*v6 + w6.y*v7 + w6.z*v8;
                acco[oc] += w6.w * v4;
            }
        }
        __syncthreads();
    }

    // --- epilogue: bias + activations + LSTM state update ---
#pragma unroll
    for (int oc = 0; oc < OCG; ++oc) {
        int occ = oc0 + oc;
        float f = sigf(accf[oc] + bf[occ]);
        float i = sigf(acci[oc] + bi[occ]);
        float g = tanhg(accg[oc] + bc[occ]);
        float o = sigf(acco[oc] + bo[occ]);
        size_t idx = (((size_t)b * HID + occ) * HH + gy) * WW + gx;
        float cn = c_prev[idx] * f + i * g;
        c_out[idx] = cn;
        h_out[idx] = tanhg(cn) * o;
    }
}

extern "C" void kernel_launch(void* const* d_in, const int* in_sizes, int n_in,
                              void* d_out, int out_size)
{
    const float* x  = (const float*)d_in[0];
    const float* Wf = (const float*)d_in[1];
    const float* bf = (const float*)d_in[2];
    const float* Wi = (const float*)d_in[3];
    const float* bi = (const float*)d_in[4];
    const float* Wc = (const float*)d_in[5];
    const float* bc = (const float*)d_in[6];
    const float* Wo = (const float*)d_in[7];
    const float* bo = (const float*)d_in[8];
    float* out = (float*)d_out;

    float* hbuf = nullptr;
    float* cbuf = nullptr;
    cudaGetSymbolAddress((void**)&hbuf, g_h);
    cudaGetSymbolAddress((void**)&cbuf, g_c);

    zero_state_kernel<<<(NOUT + 255) / 256, 256>>>();

    dim3 grid(4, 4, BB * (HID / OCG));   // 4 x 4 x 64 = 1024 blocks
    for (int t = 0; t < TT; ++t) {
        int src = t & 1, dst = src ^ 1;
        float* h_out = (t == TT - 1) ? out          : hbuf + (size_t)dst * NOUT;
        float* c_out = (t == TT - 1) ? out + NOUT   : cbuf + (size_t)dst * NOUT;
        step_kernel<<<grid, 256>>>(x, t, Wf, bf, Wi, bi, Wc, bc, Wo, bo,
                                   src, h_out, c_out);
    }
}

// round 2
// speedup vs baseline: 1.2915x; 1.2915x over previous
#include <cuda_runtime.h>
#include <math.h>

// ---------------- problem constants ----------------
#define BB   8
#define TT   16
#define CINC 16
#define HID  64
#define CH   (CINC + HID)   // 80
#define HH   64
#define WW   64
#define NPIX (HH * WW)
#define NOUT (BB * HID * NPIX)   // 2,097,152 per tensor

// tiling
#define CCH     8     // input-channel chunk (80 = 10 * 8)
#define PR      18    // patch rows  (16 + 2 halo)
#define PC      34    // patch cols  (32 + 2 halo)
#define PSTRIDE 35    // odd stride -> conflict-free LDS across half-warps

typedef unsigned long long ull;

// double-buffered recurrent state (allocation-free scratch)
__device__ float g_h[2][NOUT];
__device__ float g_c[2][NOUT];

__device__ __forceinline__ ull pack2(float v) {
    ull d; unsigned u = __float_as_uint(v);
    asm("mov.b64 %0, {%1, %1};" : "=l"(d) : "r"(u));
    return d;
}
__device__ __forceinline__ ull fma2(ull a, ull b, ull c) {
    ull d;
    asm("fma.rn.f32x2 %0, %1, %2, %3;" : "=l"(d) : "l"(a), "l"(b), "l"(c));
    return d;
}
__device__ __forceinline__ void unpack2(ull a, float& lo, float& hi) {
    unsigned l, h;
    asm("mov.b64 {%0, %1}, %2;" : "=r"(l), "=r"(h) : "l"(a));
    lo = __uint_as_float(l); hi = __uint_as_float(h);
}
__device__ __forceinline__ float sigf(float x)  { return 1.0f / (1.0f + __expf(-x)); }
__device__ __forceinline__ float tanhg(float x) { return 2.0f / (1.0f + __expf(-2.0f * x)) - 1.0f; }

__global__ void zero_state_kernel() {
    int i = blockIdx.x * blockDim.x + threadIdx.x;
    if (i < NOUT) { g_h[0][i] = 0.0f; g_c[0][i] = 0.0f; }
}

// One fused ConvLSTM step. Tile: 32x16 pixels per block; each thread computes
// 2 adjacent-x pixels for 8 output channels (as 4 oc-pairs in f32x2 lanes).
// Grid: (2, 4, BB * 8). Block: 256 threads (tx 0..15 -> x pair, ty 0..15).
__global__ __launch_bounds__(256, 2)
void step_kernel(const float* __restrict__ x, int t,
                 const float* __restrict__ Wf, const float* __restrict__ bf,
                 const float* __restrict__ Wi, const float* __restrict__ bi,
                 const float* __restrict__ Wc, const float* __restrict__ bc,
                 const float* __restrict__ Wo, const float* __restrict__ bo,
                 int src,
                 float* __restrict__ h_out, float* __restrict__ c_out)
{
    __shared__ float s_in[CCH * PR * PSTRIDE];   // 8*18*35*4 = 20160 B
    __shared__ ull   s_w[CCH * 4 * 28];          // 8*4*28*8  =  7168 B

    const int tid = threadIdx.x;
    const int tx = tid & 15, ty = tid >> 4;
    const int bx = blockIdx.x, by = blockIdx.y;
    const int b   = blockIdx.z >> 3;
    const int oc0 = (blockIdx.z & 7) * 8;

    const float* __restrict__ h_prev = g_h[src];
    const float* __restrict__ c_prev = g_c[src];

    // acc[gate][oc_pair][pixel]; gate: 0=f 1=i 2=g 3=o
    ull acc[4][4][2];
#pragma unroll
    for (int g = 0; g < 4; ++g)
#pragma unroll
        for (int j = 0; j < 4; ++j) { acc[g][j][0] = 0ull; acc[g][j][1] = 0ull; }

    for (int cb = 0; cb < CH; cb += CCH) {
        // --- cooperative load: input patch (8 ch x 18x34, zero-padded SAME) ---
        for (int i = tid; i < CCH * PR * PC; i += 256) {
            int c  = i / (PR * PC);
            int r  = i - c * (PR * PC);
            int py = r / PC, px = r - py * PC;
            int iy = by * 16 + py - 1, ix = bx * 32 + px - 1;
            float v = 0.0f;
            if ((unsigned)iy < HH && (unsigned)ix < WW) {
                int cc = cb + c;
                v = (cc < CINC)
                    ? x[(((size_t)(b * TT + t) * CINC + cc) * HH + iy) * WW + ix]
                    : h_prev[(((size_t)b * HID + (cc - CINC)) * HH + iy) * WW + ix];
            }
            s_in[c * (PR * PSTRIDE) + py * PSTRIDE + px] = v;
        }
        // --- cooperative load: weights interleaved by oc-pair ---
        // s_w[c][ocp][tap] is a 64-bit (w_oc_even, w_oc_odd) pair; tap 0..26
        // are the three conv gates (f,i,g), tap 27 is the linear o-gate weight.
        {
            float* sw = (float*)s_w;
            for (int i = tid; i < CCH * 4 * 28 * 2; i += 256) {
                int half = i & 1;
                int rest = i >> 1;
                int tap  = rest % 28;
                int ocp  = (rest / 28) & 3;
                int c    = rest / (28 * 4);
                int occ  = oc0 + ocp * 2 + half;
                int cc   = cb + c;
                float w;
                if (tap < 9)       w = Wf[(occ * CH + cc) * 9 + tap];
                else if (tap < 18) w = Wi[(occ * CH + cc) * 9 + tap - 9];
                else if (tap < 27) w = Wc[(occ * CH + cc) * 9 + tap - 18];
                else               w = Wo[occ * CH + cc];
                sw[i] = w;
            }
        }
        __syncthreads();

#pragma unroll
        for (int c = 0; c < CCH; ++c) {
            const float* pbase = &s_in[c * (PR * PSTRIDE) + ty * PSTRIDE + 2 * tx];
            // 12 input scalars -> 12 replicated 64-bit packs (ALU pipe)
            ull vp[3][4];
#pragma unroll
            for (int r = 0; r < 3; ++r)
#pragma unroll
                for (int j = 0; j < 4; ++j)
                    vp[r][j] = pack2(pbase[r * PSTRIDE + j]);

#pragma unroll
            for (int ocp = 0; ocp < 4; ++ocp) {
                const ulonglong2* wq = (const ulonglong2*)&s_w[(c * 4 + ocp) * 28];
#pragma unroll
                for (int k = 0; k < 14; ++k) {
                    ulonglong2 wv = wq[k];        // taps 2k, 2k+1 (LDS.128 broadcast)
                    {   // even tap (always < 27: conv)
                        const int tp = 2 * k;
                        const int g = tp / 9, w9 = tp % 9, r = w9 / 3, s = w9 % 3;
                        acc[g][ocp][0] = fma2(wv.x, vp[r][s],     acc[g][ocp][0]);
                        acc[g][ocp][1] = fma2(wv.x, vp[r][s + 1], acc[g][ocp][1]);
                    }
                    {   // odd tap
                        const int tp = 2 * k + 1;
                        if (tp < 27) {
                            const int g = tp / 9, w9 = tp % 9, r = w9 / 3, s = w9 % 3;
                            acc[g][ocp][0] = fma2(wv.y, vp[r][s],     acc[g][ocp][0]);
                            acc[g][ocp][1] = fma2(wv.y, vp[r][s + 1], acc[g][ocp][1]);
                        } else {
                            // tap 27: linear o-gate on center pixel
                            acc[3][ocp][0] = fma2(wv.y, vp[1][1], acc[3][ocp][0]);
                            acc[3][ocp][1] = fma2(wv.y, vp[1][2], acc[3][ocp][1]);
                        }
                    }
                }
            }
        }
        __syncthreads();
    }

    // --- epilogue: bias + activations + LSTM state update ---
    const int gy  = by * 16 + ty;
    const int gx0 = bx * 32 + 2 * tx;
#pragma unroll
    for (int ocp = 0; ocp < 4; ++ocp) {
        float af[2][2], ai[2][2], ag[2][2], ao[2][2];   // [pixel][oc_half]
#pragma unroll
        for (int p = 0; p < 2; ++p) {
            unpack2(acc[0][ocp][p], af[p][0], af[p][1]);
            unpack2(acc[1][ocp][p], ai[p][0], ai[p][1]);
            unpack2(acc[2][ocp][p], ag[p][0], ag[p][1]);
            unpack2(acc[3][ocp][p], ao[p][0], ao[p][1]);
        }
#pragma unroll
        for (int h = 0; h < 2; ++h) {
            const int occ = oc0 + ocp * 2 + h;
            const float bfv = bf[occ], biv = bi[occ], bcv = bc[occ], bov = bo[occ];
#pragma unroll
            for (int p = 0; p < 2; ++p) {
                float f = sigf(af[p][h] + bfv);
                float i = sigf(ai[p][h] + biv);
                float g = tanhg(ag[p][h] + bcv);
                float o = sigf(ao[p][h] + bov);
                size_t idx = (((size_t)b * HID + occ) * HH + gy) * WW + (gx0 + p);
                float cn = c_prev[idx] * f + i * g;
                c_out[idx] = cn;
                h_out[idx] = tanhg(cn) * o;
            }
        }
    }
}

extern "C" void kernel_launch(void* const* d_in, const int* in_sizes, int n_in,
                              void* d_out, int out_size)
{
    const float* x  = (const float*)d_in[0];
    const float* Wf = (const float*)d_in[1];
    const float* bf = (const float*)d_in[2];
    const float* Wi = (const float*)d_in[3];
    const float* bi = (const float*)d_in[4];
    const float* Wc = (const float*)d_in[5];
    const float* bc = (const float*)d_in[6];
    const float* Wo = (const float*)d_in[7];
    const float* bo = (const float*)d_in[8];
    float* out = (float*)d_out;

    float* hbuf = nullptr;
    float* cbuf = nullptr;
    cudaGetSymbolAddress((void**)&hbuf, g_h);
    cudaGetSymbolAddress((void**)&cbuf, g_c);

    zero_state_kernel<<<(NOUT + 255) / 256, 256>>>();

    dim3 grid(2, 4, BB * 8);   // 2 x 4 x 64 = 512 blocks
    for (int t = 0; t < TT; ++t) {
        int src = t & 1, dst = src ^ 1;
        float* h_out = (t == TT - 1) ? out        : hbuf + (size_t)dst * NOUT;
        float* c_out = (t == TT - 1) ? out + NOUT : cbuf + (size_t)dst * NOUT;
        step_kernel<<<grid, 256>>>(x, t, Wf, bf, Wi, bi, Wc, bc, Wo, bo,
                                   src, h_out, c_out);
    }
}